// round 2
// baseline (speedup 1.0000x reference)
#include <cuda_runtime.h>
#include <cuda_bf16.h>
#include <cstdint>

// Problem constants (fixed by the dataset)
#define N_ATOMS_MAX 50000
#define N_EDGES_MAX 640000
#define RBF 64
#define HID 128

// -------- scratch (no allocation allowed; __device__ globals) --------
__device__ __align__(16) float g_S[N_ATOMS_MAX * RBF];   // segment_sum(pair_feat)
__device__ float g_cnt[N_ATOMS_MAX];                     // edges per atom (float)
__device__ float g_Weff[RBF * HID];                      // w_rbf @ w_pair
__device__ float g_beff[HID];                            // b_rbf @ w_pair + b_pair

// ---------------------------------------------------------------
// Kernel 1: fold the two edge linear layers into one 64x128 matrix.
// grid = 65 blocks x 128 threads. Blocks 0..63 compute Weff rows,
// block 64 computes beff.
// ---------------------------------------------------------------
__global__ void prep_kernel(const float* __restrict__ w_rbf,
                            const float* __restrict__ b_rbf,
                            const float* __restrict__ w_pair,
                            const float* __restrict__ b_pair) {
    const int j = threadIdx.x;   // 0..127 (output hidden dim)
    const int r = blockIdx.x;    // 0..64
    if (r < RBF) {
        float acc = 0.f;
        #pragma unroll 8
        for (int k = 0; k < HID; ++k)
            acc += w_rbf[r * HID + k] * w_pair[k * HID + j];
        g_Weff[r * HID + j] = acc;
    } else {
        float acc = b_pair[j];
        #pragma unroll 8
        for (int k = 0; k < HID; ++k)
            acc += b_rbf[k] * w_pair[k * HID + j];
        g_beff[j] = acc;
    }
}

// ---------------------------------------------------------------
// Kernel 2: zero the scatter accumulators.
// ---------------------------------------------------------------
__global__ void zero_kernel(int n_atoms) {
    int i = blockIdx.x * blockDim.x + threadIdx.x;
    int total = n_atoms * RBF;
    if (i < total) g_S[i] = 0.f;
    if (i < n_atoms) g_cnt[i] = 0.f;
}

// ---------------------------------------------------------------
// Kernel 3: scatter-add raw pair_feat rows into g_S (vector red),
// and count edges per atom.
// 16 threads per edge; each thread owns one float4 of the 64-wide row.
// ---------------------------------------------------------------
__global__ void scatter_kernel(const float4* __restrict__ pair4,
                               const int* __restrict__ recv,
                               int n_edges) {
    int tid = blockIdx.x * blockDim.x + threadIdx.x;
    if (tid >= n_edges * 16) return;
    int e = tid >> 4;
    int s = tid & 15;
    int r = __ldg(recv + e);
    float4 v = __ldg(pair4 + tid);          // pair_feat[e, s*4 .. s*4+3]
    float* dst = g_S + (size_t)r * RBF + s * 4;
    asm volatile("red.global.add.v4.f32 [%0], {%1,%2,%3,%4};"
                 :: "l"(dst), "f"(v.x), "f"(v.y), "f"(v.z), "f"(v.w)
                 : "memory");
    if (s == 0) {
        float* c = g_cnt + r;
        asm volatile("red.global.add.f32 [%0], %1;"
                     :: "l"(c), "f"(1.0f) : "memory");
    }
}

// ---------------------------------------------------------------
// Kernel 4: atom-side fused chain, 128 atoms per block, 256 threads.
//   t1 = S_tile(128x64) @ Weff(64x128) + cnt * beff
//   h  = silu(t1 @ w1 + b1)
//   out = atom_feat + h @ w2 + b2
// Register tile: each thread computes 8 atoms x 8 outputs.
// Dynamic smem: bufA(64KB) + bufB(64KB) + wbuf(64KB) = 192KB.
// ---------------------------------------------------------------
__global__ __launch_bounds__(256, 1)
void atom_kernel(const float* __restrict__ atom_feat,
                 const float* __restrict__ w1, const float* __restrict__ b1,
                 const float* __restrict__ w2, const float* __restrict__ b2,
                 float* __restrict__ out, int n_atoms) {
    extern __shared__ float sm[];
    float* bufA = sm;                 // 128x128
    float* bufB = sm + 128 * 128;     // 128x128
    float* wbuf = sm + 2 * 128 * 128; // 128x128

    const int tid = threadIdx.x;
    const int tx = tid & 15;          // output-dim group  (j0 = tx*8)
    const int ty = tid >> 4;          // atom group        (a0 = ty*8)
    const int a0 = ty * 8;
    const int j0 = tx * 8;
    const int base = blockIdx.x * 128;

    // ---- load Weff (64x128) and the S tile (128x64) ----
    for (int i = tid; i < RBF * HID; i += 256) wbuf[i] = g_Weff[i];
    for (int i = tid; i < 128 * RBF; i += 256) {
        int a = i >> 6, k = i & 63;
        int ga = base + a;
        bufA[i] = (ga < n_atoms) ? g_S[(size_t)ga * RBF + k] : 0.f;
    }
    __syncthreads();

    float acc[8][8];

    // ================= stage 1: t1 = S @ Weff (K=64) =================
    #pragma unroll
    for (int i = 0; i < 8; ++i)
        #pragma unroll
        for (int j = 0; j < 8; ++j) acc[i][j] = 0.f;

    for (int k = 0; k < RBF; ++k) {
        const float4 w0 = reinterpret_cast<const float4*>(wbuf)[k * 32 + tx * 2];
        const float4 w1v = reinterpret_cast<const float4*>(wbuf)[k * 32 + tx * 2 + 1];
        const float wj[8] = {w0.x, w0.y, w0.z, w0.w, w1v.x, w1v.y, w1v.z, w1v.w};
        #pragma unroll
        for (int i = 0; i < 8; ++i) {
            const float x = bufA[(a0 + i) * RBF + k];
            #pragma unroll
            for (int j = 0; j < 8; ++j) acc[i][j] += x * wj[j];
        }
    }
    {
        float cl[8], bj[8];
        #pragma unroll
        for (int i = 0; i < 8; ++i) {
            int ga = base + a0 + i;
            cl[i] = (ga < n_atoms) ? g_cnt[ga] : 0.f;
        }
        #pragma unroll
        for (int j = 0; j < 8; ++j) bj[j] = g_beff[j0 + j];
        #pragma unroll
        for (int i = 0; i < 8; ++i)
            #pragma unroll
            for (int j = 0; j < 8; ++j)
                bufB[(a0 + i) * HID + j0 + j] = acc[i][j] + cl[i] * bj[j];
    }
    __syncthreads();

    // ---- load w1 ----
    for (int i = tid; i < HID * HID; i += 256) wbuf[i] = w1[i];
    __syncthreads();

    // ================= stage 2: h = silu(t1 @ w1 + b1) (K=128) =================
    #pragma unroll
    for (int i = 0; i < 8; ++i)
        #pragma unroll
        for (int j = 0; j < 8; ++j) acc[i][j] = 0.f;

    for (int k = 0; k < HID; ++k) {
        const float4 w0 = reinterpret_cast<const float4*>(wbuf)[k * 32 + tx * 2];
        const float4 w1v = reinterpret_cast<const float4*>(wbuf)[k * 32 + tx * 2 + 1];
        const float wj[8] = {w0.x, w0.y, w0.z, w0.w, w1v.x, w1v.y, w1v.z, w1v.w};
        #pragma unroll
        for (int i = 0; i < 8; ++i) {
            const float x = bufB[(a0 + i) * HID + k];
            #pragma unroll
            for (int j = 0; j < 8; ++j) acc[i][j] += x * wj[j];
        }
    }
    {
        float bj[8];
        #pragma unroll
        for (int j = 0; j < 8; ++j) bj[j] = b1[j0 + j];
        #pragma unroll
        for (int i = 0; i < 8; ++i)
            #pragma unroll
            for (int j = 0; j < 8; ++j) {
                float v = acc[i][j] + bj[j];
                bufA[(a0 + i) * HID + j0 + j] = v / (1.f + __expf(-v));
            }
    }
    __syncthreads();

    // ---- load w2 ----
    for (int i = tid; i < HID * HID; i += 256) wbuf[i] = w2[i];
    __syncthreads();

    // ================= stage 3: out = atom_feat + h @ w2 + b2 (K=128) =================
    #pragma unroll
    for (int i = 0; i < 8; ++i)
        #pragma unroll
        for (int j = 0; j < 8; ++j) acc[i][j] = 0.f;

    for (int k = 0; k < HID; ++k) {
        const float4 w0 = reinterpret_cast<const float4*>(wbuf)[k * 32 + tx * 2];
        const float4 w1v = reinterpret_cast<const float4*>(wbuf)[k * 32 + tx * 2 + 1];
        const float wj[8] = {w0.x, w0.y, w0.z, w0.w, w1v.x, w1v.y, w1v.z, w1v.w};
        #pragma unroll
        for (int i = 0; i < 8; ++i) {
            const float x = bufA[(a0 + i) * HID + k];
            #pragma unroll
            for (int j = 0; j < 8; ++j) acc[i][j] += x * wj[j];
        }
    }
    {
        float bj[8];
        #pragma unroll
        for (int j = 0; j < 8; ++j) bj[j] = b2[j0 + j];
        #pragma unroll
        for (int i = 0; i < 8; ++i) {
            int ga = base + a0 + i;
            if (ga >= n_atoms) continue;
            const float4* af = reinterpret_cast<const float4*>(atom_feat + (size_t)ga * HID + j0);
            float4* op = reinterpret_cast<float4*>(out + (size_t)ga * HID + j0);
            float4 f0 = __ldg(af);
            float4 f1 = __ldg(af + 1);
            float4 o0, o1;
            o0.x = f0.x + acc[i][0] + bj[0];
            o0.y = f0.y + acc[i][1] + bj[1];
            o0.z = f0.z + acc[i][2] + bj[2];
            o0.w = f0.w + acc[i][3] + bj[3];
            o1.x = f1.x + acc[i][4] + bj[4];
            o1.y = f1.y + acc[i][5] + bj[5];
            o1.z = f1.z + acc[i][6] + bj[6];
            o1.w = f1.w + acc[i][7] + bj[7];
            op[0] = o0;
            op[1] = o1;
        }
    }
}

// ---------------------------------------------------------------
// launch
// Inputs (metadata order): atom_feat, pair_feat, recv_idx, w_rbf, b_rbf,
//                          w_pair, b_pair, w1, b1, w2, b2
// ---------------------------------------------------------------
extern "C" void kernel_launch(void* const* d_in, const int* in_sizes, int n_in,
                              void* d_out, int out_size) {
    const float* atom_feat = (const float*)d_in[0];
    const float* pair_feat = (const float*)d_in[1];
    const int*   recv_idx  = (const int*)d_in[2];
    const float* w_rbf     = (const float*)d_in[3];
    const float* b_rbf     = (const float*)d_in[4];
    const float* w_pair    = (const float*)d_in[5];
    const float* b_pair    = (const float*)d_in[6];
    const float* w1        = (const float*)d_in[7];
    const float* b1        = (const float*)d_in[8];
    const float* w2        = (const float*)d_in[9];
    const float* b2        = (const float*)d_in[10];
    float* out = (float*)d_out;

    const int n_atoms = in_sizes[0] / HID;
    const int n_edges = in_sizes[2];

    // 1) fold edge linear layers
    prep_kernel<<<RBF + 1, HID>>>(w_rbf, b_rbf, w_pair, b_pair);

    // 2) zero accumulators
    {
        int total = n_atoms * RBF;
        int blocks = (total + 255) / 256;
        zero_kernel<<<blocks, 256>>>(n_atoms);
    }

    // 3) scatter pair_feat into S + edge counts
    {
        long long threads = (long long)n_edges * 16;
        int blocks = (int)((threads + 255) / 256);
        scatter_kernel<<<blocks, 256>>>((const float4*)pair_feat, recv_idx, n_edges);
    }

    // 4) fused atom-side chain
    {
        static bool attr_set = false;
        if (!attr_set) {
            cudaFuncSetAttribute(atom_kernel,
                                 cudaFuncAttributeMaxDynamicSharedMemorySize,
                                 3 * 128 * 128 * sizeof(float));
            attr_set = true;
        }
        int blocks = (n_atoms + 127) / 128;
        atom_kernel<<<blocks, 256, 3 * 128 * 128 * sizeof(float)>>>(
            atom_feat, w1, b1, w2, b2, out, n_atoms);
    }
}

// round 3
// speedup vs baseline: 1.6288x; 1.6288x over previous
#include <cuda_runtime.h>
#include <cuda_bf16.h>
#include <cstdint>

// Problem constants (fixed by the dataset)
#define N_ATOMS_MAX 50000
#define N_EDGES_MAX 640000
#define RBF 64
#define HID 128
#define LDA 132   // padded smem stride (floats) -> conflict-free tf32 fragment loads

// -------- scratch (no allocation allowed; __device__ globals) --------
__device__ __align__(16) float g_S[N_ATOMS_MAX * RBF];   // segment_sum(pair_feat)
__device__ float g_cnt[N_ATOMS_MAX];                     // edges per atom (float)
__device__ float g_Weff[RBF * HID];                      // w_rbf @ w_pair
__device__ float g_beff[HID];                            // b_rbf @ w_pair + b_pair

// ---------------------------------------------------------------
// helpers
// ---------------------------------------------------------------
__device__ __forceinline__ uint32_t f2tf32(float f) {
    uint32_t r;
    asm("cvt.rna.tf32.f32 %0, %1;" : "=r"(r) : "f"(f));
    return r;
}

__device__ __forceinline__ void mma_tf32(float* d, const uint32_t* a, const uint32_t* b) {
    asm volatile(
        "mma.sync.aligned.m16n8k8.row.col.f32.tf32.tf32.f32 "
        "{%0,%1,%2,%3}, {%4,%5,%6,%7}, {%8,%9}, {%0,%1,%2,%3};"
        : "+f"(d[0]), "+f"(d[1]), "+f"(d[2]), "+f"(d[3])
        : "r"(a[0]), "r"(a[1]), "r"(a[2]), "r"(a[3]),
          "r"(b[0]), "r"(b[1]));
}

// ---------------------------------------------------------------
// Kernel 1: fold the two edge linear layers into one 64x128 matrix.
// ---------------------------------------------------------------
__global__ void prep_kernel(const float* __restrict__ w_rbf,
                            const float* __restrict__ b_rbf,
                            const float* __restrict__ w_pair,
                            const float* __restrict__ b_pair) {
    const int j = threadIdx.x;   // 0..127
    const int r = blockIdx.x;    // 0..64
    if (r < RBF) {
        float acc = 0.f;
        #pragma unroll 8
        for (int k = 0; k < HID; ++k)
            acc += w_rbf[r * HID + k] * w_pair[k * HID + j];
        g_Weff[r * HID + j] = acc;
    } else {
        float acc = b_pair[j];
        #pragma unroll 8
        for (int k = 0; k < HID; ++k)
            acc += b_rbf[k] * w_pair[k * HID + j];
        g_beff[j] = acc;
    }
}

// ---------------------------------------------------------------
// Kernel 2: zero the scatter accumulators.
// ---------------------------------------------------------------
__global__ void zero_kernel(int n_atoms) {
    int i = blockIdx.x * blockDim.x + threadIdx.x;
    int total = n_atoms * RBF;
    if (i < total) g_S[i] = 0.f;
    if (i < n_atoms) g_cnt[i] = 0.f;
}

// ---------------------------------------------------------------
// Kernel 3: scatter-add raw pair_feat rows into g_S + edge counts.
// 16 threads per edge; each thread owns one float4 of the 64-wide row.
// ---------------------------------------------------------------
__global__ void scatter_kernel(const float4* __restrict__ pair4,
                               const int* __restrict__ recv,
                               int n_edges) {
    int tid = blockIdx.x * blockDim.x + threadIdx.x;
    if (tid >= n_edges * 16) return;
    int e = tid >> 4;
    int s = tid & 15;
    int r = __ldg(recv + e);
    float4 v = __ldg(pair4 + tid);
    float* dst = g_S + (size_t)r * RBF + s * 4;
    asm volatile("red.global.add.v4.f32 [%0], {%1,%2,%3,%4};"
                 :: "l"(dst), "f"(v.x), "f"(v.y), "f"(v.z), "f"(v.w)
                 : "memory");
    if (s == 0) {
        float* c = g_cnt + r;
        asm volatile("red.global.add.f32 [%0], %1;"
                     :: "l"(c), "f"(1.0f) : "memory");
    }
}

// ---------------------------------------------------------------
// Kernel 4: atom-side fused chain on the TENSOR pipe (tf32 mma.sync).
// 128 atoms x 128 outputs per block, 256 threads = 8 warps.
// Warp grid 4(M) x 2(N): each warp owns a 32x64 C tile
//   = 2 m16-tiles x 8 n8-tiles of m16n8k8.
// Stages chained through padded smem buffers (values staged as tf32).
// ---------------------------------------------------------------
__global__ __launch_bounds__(256, 1)
void atom_kernel(const float* __restrict__ atom_feat,
                 const float* __restrict__ w1, const float* __restrict__ b1,
                 const float* __restrict__ w2, const float* __restrict__ b2,
                 float* __restrict__ out, int n_atoms) {
    extern __shared__ uint32_t sm[];
    uint32_t* bufA = sm;                 // 128 x LDA activations (tf32 bits)
    uint32_t* bufB = sm + 128 * LDA;     // 128 x LDA
    uint32_t* wbuf = sm + 2 * 128 * LDA; // 128 x LDA weights, [k][n]

    const int tid  = threadIdx.x;
    const int lane = tid & 31;
    const int wid  = tid >> 5;
    const int warp_m = wid & 3;   // row band: 32*warp_m
    const int warp_n = wid >> 2;  // col band: 64*warp_n
    const int gp = lane >> 2;     // groupID 0..7
    const int tg = lane & 3;      // thread-in-group 0..3
    const int base = blockIdx.x * 128;

    // fragment base offsets
    const int m0 = warp_m * 32;
    const int n0 = warp_n * 64;
    const int aoff = (m0 + gp) * LDA + tg;        // + mt*16*LDA + ks*8 (+4 / +8*LDA)
    const int boff = tg * LDA + n0 + gp;          // + ks*8*LDA + nt*8 (+4*LDA)

    float acc[2][8][4];

    // ---- stage weights: Weff (64x128) ----
    for (int i = tid; i < RBF * HID; i += 256) {
        int r = i >> 7, c = i & 127;
        wbuf[r * LDA + c] = f2tf32(g_Weff[i]);
    }
    // ---- stage activations: S tile (128 x 64) ----
    for (int i = tid; i < 128 * RBF; i += 256) {
        int a = i >> 6, k = i & 63;
        int ga = base + a;
        bufA[a * LDA + k] = f2tf32((ga < n_atoms) ? g_S[(size_t)ga * RBF + k] : 0.f);
    }
    __syncthreads();

    // ================= stage 1: t1 = S @ Weff  (K=64) =================
    #pragma unroll
    for (int mt = 0; mt < 2; ++mt)
        #pragma unroll
        for (int nt = 0; nt < 8; ++nt)
            #pragma unroll
            for (int q = 0; q < 4; ++q) acc[mt][nt][q] = 0.f;

    #pragma unroll
    for (int ks = 0; ks < 8; ++ks) {
        uint32_t a[2][4], b[8][2];
        #pragma unroll
        for (int mt = 0; mt < 2; ++mt) {
            int o = aoff + mt * 16 * LDA + ks * 8;
            a[mt][0] = bufA[o];
            a[mt][1] = bufA[o + 8 * LDA];
            a[mt][2] = bufA[o + 4];
            a[mt][3] = bufA[o + 8 * LDA + 4];
        }
        #pragma unroll
        for (int nt = 0; nt < 8; ++nt) {
            int o = boff + ks * 8 * LDA + nt * 8;
            b[nt][0] = wbuf[o];
            b[nt][1] = wbuf[o + 4 * LDA];
        }
        #pragma unroll
        for (int mt = 0; mt < 2; ++mt)
            #pragma unroll
            for (int nt = 0; nt < 8; ++nt)
                mma_tf32(acc[mt][nt], a[mt], b[nt]);
    }

    // epilogue 1: + cnt * beff, store t1 -> bufB (tf32)
    {
        float cntv[2][2];
        #pragma unroll
        for (int mt = 0; mt < 2; ++mt) {
            int r0 = base + m0 + mt * 16 + gp;
            cntv[mt][0] = (r0 < n_atoms) ? __ldg(g_cnt + r0) : 0.f;
            cntv[mt][1] = (r0 + 8 < n_atoms) ? __ldg(g_cnt + r0 + 8) : 0.f;
        }
        #pragma unroll
        for (int nt = 0; nt < 8; ++nt) {
            int c = n0 + nt * 8 + 2 * tg;
            float be0 = g_beff[c], be1 = g_beff[c + 1];
            #pragma unroll
            for (int mt = 0; mt < 2; ++mt) {
                int r = m0 + mt * 16 + gp;
                bufB[r * LDA + c]           = f2tf32(acc[mt][nt][0] + cntv[mt][0] * be0);
                bufB[r * LDA + c + 1]       = f2tf32(acc[mt][nt][1] + cntv[mt][0] * be1);
                bufB[(r + 8) * LDA + c]     = f2tf32(acc[mt][nt][2] + cntv[mt][1] * be0);
                bufB[(r + 8) * LDA + c + 1] = f2tf32(acc[mt][nt][3] + cntv[mt][1] * be1);
            }
        }
    }
    __syncthreads();

    // ---- stage weights: w1 ----
    for (int i = tid; i < HID * HID; i += 256) {
        int r = i >> 7, c = i & 127;
        wbuf[r * LDA + c] = f2tf32(w1[i]);
    }
    __syncthreads();

    // ================= stage 2: h = silu(t1 @ w1 + b1)  (K=128) =================
    #pragma unroll
    for (int mt = 0; mt < 2; ++mt)
        #pragma unroll
        for (int nt = 0; nt < 8; ++nt)
            #pragma unroll
            for (int q = 0; q < 4; ++q) acc[mt][nt][q] = 0.f;

    #pragma unroll 4
    for (int ks = 0; ks < 16; ++ks) {
        uint32_t a[2][4], b[8][2];
        #pragma unroll
        for (int mt = 0; mt < 2; ++mt) {
            int o = aoff + mt * 16 * LDA + ks * 8;
            a[mt][0] = bufB[o];
            a[mt][1] = bufB[o + 8 * LDA];
            a[mt][2] = bufB[o + 4];
            a[mt][3] = bufB[o + 8 * LDA + 4];
        }
        #pragma unroll
        for (int nt = 0; nt < 8; ++nt) {
            int o = boff + ks * 8 * LDA + nt * 8;
            b[nt][0] = wbuf[o];
            b[nt][1] = wbuf[o + 4 * LDA];
        }
        #pragma unroll
        for (int mt = 0; mt < 2; ++mt)
            #pragma unroll
            for (int nt = 0; nt < 8; ++nt)
                mma_tf32(acc[mt][nt], a[mt], b[nt]);
    }

    // epilogue 2: bias + silu, store h -> bufA (tf32)
    #pragma unroll
    for (int nt = 0; nt < 8; ++nt) {
        int c = n0 + nt * 8 + 2 * tg;
        float b10 = __ldg(b1 + c), b11 = __ldg(b1 + c + 1);
        #pragma unroll
        for (int mt = 0; mt < 2; ++mt) {
            int r = m0 + mt * 16 + gp;
            float v0 = acc[mt][nt][0] + b10;
            float v1 = acc[mt][nt][1] + b11;
            float v2 = acc[mt][nt][2] + b10;
            float v3 = acc[mt][nt][3] + b11;
            bufA[r * LDA + c]           = f2tf32(v0 / (1.f + __expf(-v0)));
            bufA[r * LDA + c + 1]       = f2tf32(v1 / (1.f + __expf(-v1)));
            bufA[(r + 8) * LDA + c]     = f2tf32(v2 / (1.f + __expf(-v2)));
            bufA[(r + 8) * LDA + c + 1] = f2tf32(v3 / (1.f + __expf(-v3)));
        }
    }
    __syncthreads();

    // ---- stage weights: w2 ----
    for (int i = tid; i < HID * HID; i += 256) {
        int r = i >> 7, c = i & 127;
        wbuf[r * LDA + c] = f2tf32(w2[i]);
    }
    __syncthreads();

    // ================= stage 3: out = atom_feat + h @ w2 + b2  (K=128) =================
    #pragma unroll
    for (int mt = 0; mt < 2; ++mt)
        #pragma unroll
        for (int nt = 0; nt < 8; ++nt)
            #pragma unroll
            for (int q = 0; q < 4; ++q) acc[mt][nt][q] = 0.f;

    #pragma unroll 4
    for (int ks = 0; ks < 16; ++ks) {
        uint32_t a[2][4], b[8][2];
        #pragma unroll
        for (int mt = 0; mt < 2; ++mt) {
            int o = aoff + mt * 16 * LDA + ks * 8;
            a[mt][0] = bufA[o];
            a[mt][1] = bufA[o + 8 * LDA];
            a[mt][2] = bufA[o + 4];
            a[mt][3] = bufA[o + 8 * LDA + 4];
        }
        #pragma unroll
        for (int nt = 0; nt < 8; ++nt) {
            int o = boff + ks * 8 * LDA + nt * 8;
            b[nt][0] = wbuf[o];
            b[nt][1] = wbuf[o + 4 * LDA];
        }
        #pragma unroll
        for (int mt = 0; mt < 2; ++mt)
            #pragma unroll
            for (int nt = 0; nt < 8; ++nt)
                mma_tf32(acc[mt][nt], a[mt], b[nt]);
    }

    // epilogue 3: + atom_feat + b2, write out (float2, coalesced 32B per 4 lanes)
    #pragma unroll
    for (int nt = 0; nt < 8; ++nt) {
        int c = n0 + nt * 8 + 2 * tg;
        float b20 = __ldg(b2 + c), b21 = __ldg(b2 + c + 1);
        #pragma unroll
        for (int mt = 0; mt < 2; ++mt) {
            int r = m0 + mt * 16 + gp;
            int ga0 = base + r;
            int ga1 = ga0 + 8;
            if (ga0 < n_atoms) {
                float2 af = *reinterpret_cast<const float2*>(atom_feat + (size_t)ga0 * HID + c);
                float2 o0;
                o0.x = af.x + acc[mt][nt][0] + b20;
                o0.y = af.y + acc[mt][nt][1] + b21;
                *reinterpret_cast<float2*>(out + (size_t)ga0 * HID + c) = o0;
            }
            if (ga1 < n_atoms) {
                float2 af = *reinterpret_cast<const float2*>(atom_feat + (size_t)ga1 * HID + c);
                float2 o1;
                o1.x = af.x + acc[mt][nt][2] + b20;
                o1.y = af.y + acc[mt][nt][3] + b21;
                *reinterpret_cast<float2*>(out + (size_t)ga1 * HID + c) = o1;
            }
        }
    }
}

// ---------------------------------------------------------------
// launch
// Inputs (metadata order): atom_feat, pair_feat, recv_idx, w_rbf, b_rbf,
//                          w_pair, b_pair, w1, b1, w2, b2
// ---------------------------------------------------------------
extern "C" void kernel_launch(void* const* d_in, const int* in_sizes, int n_in,
                              void* d_out, int out_size) {
    const float* atom_feat = (const float*)d_in[0];
    const float* pair_feat = (const float*)d_in[1];
    const int*   recv_idx  = (const int*)d_in[2];
    const float* w_rbf     = (const float*)d_in[3];
    const float* b_rbf     = (const float*)d_in[4];
    const float* w_pair    = (const float*)d_in[5];
    const float* b_pair    = (const float*)d_in[6];
    const float* w1        = (const float*)d_in[7];
    const float* b1        = (const float*)d_in[8];
    const float* w2        = (const float*)d_in[9];
    const float* b2        = (const float*)d_in[10];
    float* out = (float*)d_out;

    const int n_atoms = in_sizes[0] / HID;
    const int n_edges = in_sizes[2];

    // 1) fold edge linear layers
    prep_kernel<<<RBF + 1, HID>>>(w_rbf, b_rbf, w_pair, b_pair);

    // 2) zero accumulators
    {
        int total = n_atoms * RBF;
        int blocks = (total + 255) / 256;
        zero_kernel<<<blocks, 256>>>(n_atoms);
    }

    // 3) scatter pair_feat into S + edge counts
    {
        long long threads = (long long)n_edges * 16;
        int blocks = (int)((threads + 255) / 256);
        scatter_kernel<<<blocks, 256>>>((const float4*)pair_feat, recv_idx, n_edges);
    }

    // 4) fused atom-side chain on tensor cores
    {
        const int smem_bytes = 3 * 128 * LDA * sizeof(uint32_t);  // ~198 KB
        static bool attr_set = false;
        if (!attr_set) {
            cudaFuncSetAttribute(atom_kernel,
                                 cudaFuncAttributeMaxDynamicSharedMemorySize,
                                 smem_bytes);
            attr_set = true;
        }
        int blocks = (n_atoms + 127) / 128;
        atom_kernel<<<blocks, 256, smem_bytes>>>(
            atom_feat, w1, b1, w2, b2, out, n_atoms);
    }
}

// round 4
// speedup vs baseline: 1.9486x; 1.1964x over previous
#include <cuda_runtime.h>
#include <cuda_bf16.h>
#include <cstdint>

// Problem constants (fixed by the dataset)
#define N_ATOMS_MAX 50000
#define N_EDGES_MAX 640000
#define RBF 64
#define HID 128
#define LDA 132   // padded smem stride (floats) -> conflict-free fragment loads

// -------- scratch (no allocation allowed; __device__ globals) --------
__device__ __align__(16) float g_S[N_ATOMS_MAX * RBF];   // segment_sum(pair_feat)
__device__ float g_cnt[N_ATOMS_MAX];                     // edges per atom (float)
__device__ __align__(16) float g_Weff[RBF * HID];        // w_rbf @ w_pair
__device__ float g_beff[HID];                            // b_rbf @ w_pair + b_pair

// ---------------------------------------------------------------
// helpers
// ---------------------------------------------------------------
__device__ __forceinline__ uint32_t f2tf32(float f) {
    uint32_t r;
    asm("cvt.rna.tf32.f32 %0, %1;" : "=r"(r) : "f"(f));
    return r;
}

__device__ __forceinline__ void mma_tf32(float* d, const uint32_t* a, const uint32_t* b) {
    asm volatile(
        "mma.sync.aligned.m16n8k8.row.col.f32.tf32.tf32.f32 "
        "{%0,%1,%2,%3}, {%4,%5,%6,%7}, {%8,%9}, {%0,%1,%2,%3};"
        : "+f"(d[0]), "+f"(d[1]), "+f"(d[2]), "+f"(d[3])
        : "r"(a[0]), "r"(a[1]), "r"(a[2]), "r"(a[3]),
          "r"(b[0]), "r"(b[1]));
}

__device__ __forceinline__ void cp16(uint32_t dst_smem, const void* src) {
    asm volatile("cp.async.cg.shared.global [%0], [%1], 16;"
                 :: "r"(dst_smem), "l"(src));
}
__device__ __forceinline__ void cp_commit() {
    asm volatile("cp.async.commit_group;");
}
template <int N>
__device__ __forceinline__ void cp_wait() {
    asm volatile("cp.async.wait_group %0;" :: "n"(N));
}

// ---------------------------------------------------------------
// Kernel 1: fold the two edge linear layers into one 64x128 matrix.
// ---------------------------------------------------------------
__global__ void prep_kernel(const float* __restrict__ w_rbf,
                            const float* __restrict__ b_rbf,
                            const float* __restrict__ w_pair,
                            const float* __restrict__ b_pair) {
    const int j = threadIdx.x;   // 0..127
    const int r = blockIdx.x;    // 0..64
    if (r < RBF) {
        float acc = 0.f;
        #pragma unroll 8
        for (int k = 0; k < HID; ++k)
            acc += w_rbf[r * HID + k] * w_pair[k * HID + j];
        g_Weff[r * HID + j] = acc;
    } else {
        float acc = b_pair[j];
        #pragma unroll 8
        for (int k = 0; k < HID; ++k)
            acc += b_rbf[k] * w_pair[k * HID + j];
        g_beff[j] = acc;
    }
}

// ---------------------------------------------------------------
// Kernel 2: zero the scatter accumulators.
// ---------------------------------------------------------------
__global__ void zero_kernel(int n_atoms) {
    int i = blockIdx.x * blockDim.x + threadIdx.x;
    int total = n_atoms * RBF;
    if (i < total) g_S[i] = 0.f;
    if (i < n_atoms) g_cnt[i] = 0.f;
}

// ---------------------------------------------------------------
// Kernel 3: scatter-add raw pair_feat rows into g_S + edge counts.
// ---------------------------------------------------------------
__global__ void scatter_kernel(const float4* __restrict__ pair4,
                               const int* __restrict__ recv,
                               int n_edges) {
    int tid = blockIdx.x * blockDim.x + threadIdx.x;
    if (tid >= n_edges * 16) return;
    int e = tid >> 4;
    int s = tid & 15;
    int r = __ldg(recv + e);
    float4 v = __ldg(pair4 + tid);
    float* dst = g_S + (size_t)r * RBF + s * 4;
    asm volatile("red.global.add.v4.f32 [%0], {%1,%2,%3,%4};"
                 :: "l"(dst), "f"(v.x), "f"(v.y), "f"(v.z), "f"(v.w)
                 : "memory");
    if (s == 0) {
        float* c = g_cnt + r;
        asm volatile("red.global.add.f32 [%0], %1;"
                     :: "l"(c), "f"(1.0f) : "memory");
    }
}

// ---------------------------------------------------------------
// Kernel 4: atom-side fused chain, tf32 mma, 512 threads = 16 warps.
// Warp grid 8(M) x 2(N): each warp owns a 16x64 C tile.
// Single activation buffer (in-place between stages) + two weight
// buffers with cp.async pipelining:
//   G0: Weff+S   G1: w1 (lands during stage1)   G2: w2 (during stage2)
// ---------------------------------------------------------------
__global__ __launch_bounds__(512, 1)
void atom_kernel(const float* __restrict__ atom_feat,
                 const float* __restrict__ w1, const float* __restrict__ b1,
                 const float* __restrict__ w2, const float* __restrict__ b2,
                 float* __restrict__ out, int n_atoms) {
    extern __shared__ uint32_t sm[];
    uint32_t* buf = sm;                 // 128 x LDA activations
    uint32_t* wX  = sm + 128 * LDA;     // Weff, later w2
    uint32_t* wY  = sm + 2 * 128 * LDA; // w1

    const int tid  = threadIdx.x;
    const int lane = tid & 31;
    const int wid  = tid >> 5;
    const int warp_m = wid & 7;   // row band: 16*warp_m
    const int warp_n = wid >> 3;  // col band: 64*warp_n
    const int gp = lane >> 2;     // 0..7
    const int tg = lane & 3;      // 0..3
    const int base = blockIdx.x * 128;
    const int valid = n_atoms - base;          // rows in this tile (<=128)

    const int m0 = warp_m * 16;
    const int n0 = warp_n * 64;
    const int aoff = (m0 + gp) * LDA + tg;
    const int boff = tg * LDA + n0 + gp;

    const uint32_t sbase = (uint32_t)__cvta_generic_to_shared(sm);
    const uint32_t s_buf = sbase;
    const uint32_t s_wX  = sbase + 128 * LDA * 4;
    const uint32_t s_wY  = sbase + 2 * 128 * LDA * 4;

    // ---- G0: Weff (64x128) + S tile (128x64) ----
    #pragma unroll
    for (int it = 0; it < 4; ++it) {
        int c = tid + it * 512;            // 2048 chunks
        int r = c >> 5, q = c & 31;        // q: 16B unit
        cp16(s_wX + (r * LDA + q * 4) * 4, g_Weff + r * HID + q * 4);
    }
    #pragma unroll
    for (int it = 0; it < 4; ++it) {
        int c = tid + it * 512;            // 2048 chunks
        int r = c >> 4, q = c & 15;
        if (r < valid)
            cp16(s_buf + (r * LDA + q * 4) * 4, g_S + (size_t)(base + r) * RBF + q * 4);
    }
    cp_commit();
    // ---- G1: w1 (128x128) ----
    #pragma unroll
    for (int it = 0; it < 8; ++it) {
        int c = tid + it * 512;            // 4096 chunks
        int r = c >> 5, q = c & 31;
        cp16(s_wY + (r * LDA + q * 4) * 4, w1 + r * HID + q * 4);
    }
    cp_commit();

    cp_wait<1>();                          // G0 arrived
    if (valid < 128) {                     // zero-pad tail rows (rare: 1 block)
        for (int i = tid; i < 128 * RBF; i += 512) {
            int r = i >> 6;
            if (r >= valid) buf[r * LDA + (i & 63)] = 0;
        }
    }
    __syncthreads();

    float acc[8][4];

    // ================= stage 1: t1 = S @ Weff  (K=64) =================
    #pragma unroll
    for (int nt = 0; nt < 8; ++nt)
        #pragma unroll
        for (int q = 0; q < 4; ++q) acc[nt][q] = 0.f;

    #pragma unroll
    for (int ks = 0; ks < 8; ++ks) {
        uint32_t a[4], b[8][2];
        int o = aoff + ks * 8;
        a[0] = buf[o];
        a[1] = buf[o + 8 * LDA];
        a[2] = buf[o + 4];
        a[3] = buf[o + 8 * LDA + 4];
        #pragma unroll
        for (int nt = 0; nt < 8; ++nt) {
            int ob = boff + ks * 8 * LDA + nt * 8;
            b[nt][0] = wX[ob];
            b[nt][1] = wX[ob + 4 * LDA];
        }
        #pragma unroll
        for (int nt = 0; nt < 8; ++nt)
            mma_tf32(acc[nt], a, b[nt]);
    }
    __syncthreads();                       // all reads of buf & wX done

    // ---- G2: w2 -> wX (overlaps stage 2) ----
    #pragma unroll
    for (int it = 0; it < 8; ++it) {
        int c = tid + it * 512;
        int r = c >> 5, q = c & 31;
        cp16(s_wX + (r * LDA + q * 4) * 4, w2 + r * HID + q * 4);
    }
    cp_commit();

    // epilogue 1: + cnt * beff, t1 -> buf (in place)
    {
        int r0 = base + m0 + gp;
        float c0 = (r0 < n_atoms) ? __ldg(g_cnt + r0) : 0.f;
        float c1 = (r0 + 8 < n_atoms) ? __ldg(g_cnt + r0 + 8) : 0.f;
        #pragma unroll
        for (int nt = 0; nt < 8; ++nt) {
            int c = n0 + nt * 8 + 2 * tg;
            float be0 = g_beff[c], be1 = g_beff[c + 1];
            int r = m0 + gp;
            buf[r * LDA + c]           = f2tf32(acc[nt][0] + c0 * be0);
            buf[r * LDA + c + 1]       = f2tf32(acc[nt][1] + c0 * be1);
            buf[(r + 8) * LDA + c]     = f2tf32(acc[nt][2] + c1 * be0);
            buf[(r + 8) * LDA + c + 1] = f2tf32(acc[nt][3] + c1 * be1);
        }
    }
    cp_wait<1>();                          // G1 (w1) arrived; G2 may pend
    __syncthreads();

    // ================= stage 2: h = silu(t1 @ w1 + b1)  (K=128) =================
    #pragma unroll
    for (int nt = 0; nt < 8; ++nt)
        #pragma unroll
        for (int q = 0; q < 4; ++q) acc[nt][q] = 0.f;

    #pragma unroll 4
    for (int ks = 0; ks < 16; ++ks) {
        uint32_t a[4], b[8][2];
        int o = aoff + ks * 8;
        a[0] = buf[o];
        a[1] = buf[o + 8 * LDA];
        a[2] = buf[o + 4];
        a[3] = buf[o + 8 * LDA + 4];
        #pragma unroll
        for (int nt = 0; nt < 8; ++nt) {
            int ob = boff + ks * 8 * LDA + nt * 8;
            b[nt][0] = wY[ob];
            b[nt][1] = wY[ob + 4 * LDA];
        }
        #pragma unroll
        for (int nt = 0; nt < 8; ++nt)
            mma_tf32(acc[nt], a, b[nt]);
    }
    __syncthreads();                       // all reads of buf done

    // epilogue 2: bias + silu -> buf (in place)
    #pragma unroll
    for (int nt = 0; nt < 8; ++nt) {
        int c = n0 + nt * 8 + 2 * tg;
        float b10 = __ldg(b1 + c), b11 = __ldg(b1 + c + 1);
        int r = m0 + gp;
        float v0 = acc[nt][0] + b10;
        float v1 = acc[nt][1] + b11;
        float v2 = acc[nt][2] + b10;
        float v3 = acc[nt][3] + b11;
        buf[r * LDA + c]           = f2tf32(v0 / (1.f + __expf(-v0)));
        buf[r * LDA + c + 1]       = f2tf32(v1 / (1.f + __expf(-v1)));
        buf[(r + 8) * LDA + c]     = f2tf32(v2 / (1.f + __expf(-v2)));
        buf[(r + 8) * LDA + c + 1] = f2tf32(v3 / (1.f + __expf(-v3)));
    }
    cp_wait<0>();                          // G2 (w2) arrived
    __syncthreads();

    // ================= stage 3: out = atom_feat + h @ w2 + b2  (K=128) =================
    #pragma unroll
    for (int nt = 0; nt < 8; ++nt)
        #pragma unroll
        for (int q = 0; q < 4; ++q) acc[nt][q] = 0.f;

    #pragma unroll 4
    for (int ks = 0; ks < 16; ++ks) {
        uint32_t a[4], b[8][2];
        int o = aoff + ks * 8;
        a[0] = buf[o];
        a[1] = buf[o + 8 * LDA];
        a[2] = buf[o + 4];
        a[3] = buf[o + 8 * LDA + 4];
        #pragma unroll
        for (int nt = 0; nt < 8; ++nt) {
            int ob = boff + ks * 8 * LDA + nt * 8;
            b[nt][0] = wX[ob];
            b[nt][1] = wX[ob + 4 * LDA];
        }
        #pragma unroll
        for (int nt = 0; nt < 8; ++nt)
            mma_tf32(acc[nt], a, b[nt]);
    }

    // epilogue 3: + atom_feat + b2, write out
    #pragma unroll
    for (int nt = 0; nt < 8; ++nt) {
        int c = n0 + nt * 8 + 2 * tg;
        float b20 = __ldg(b2 + c), b21 = __ldg(b2 + c + 1);
        int r = m0 + gp;
        int ga0 = base + r;
        int ga1 = ga0 + 8;
        if (ga0 < n_atoms) {
            float2 af = *reinterpret_cast<const float2*>(atom_feat + (size_t)ga0 * HID + c);
            float2 o0;
            o0.x = af.x + acc[nt][0] + b20;
            o0.y = af.y + acc[nt][1] + b21;
            *reinterpret_cast<float2*>(out + (size_t)ga0 * HID + c) = o0;
        }
        if (ga1 < n_atoms) {
            float2 af = *reinterpret_cast<const float2*>(atom_feat + (size_t)ga1 * HID + c);
            float2 o1;
            o1.x = af.x + acc[nt][2] + b20;
            o1.y = af.y + acc[nt][3] + b21;
            *reinterpret_cast<float2*>(out + (size_t)ga1 * HID + c) = o1;
        }
    }
}

// ---------------------------------------------------------------
// launch
// Inputs: atom_feat, pair_feat, recv_idx, w_rbf, b_rbf,
//         w_pair, b_pair, w1, b1, w2, b2
// ---------------------------------------------------------------
extern "C" void kernel_launch(void* const* d_in, const int* in_sizes, int n_in,
                              void* d_out, int out_size) {
    const float* atom_feat = (const float*)d_in[0];
    const float* pair_feat = (const float*)d_in[1];
    const int*   recv_idx  = (const int*)d_in[2];
    const float* w_rbf     = (const float*)d_in[3];
    const float* b_rbf     = (const float*)d_in[4];
    const float* w_pair    = (const float*)d_in[5];
    const float* b_pair    = (const float*)d_in[6];
    const float* w1        = (const float*)d_in[7];
    const float* b1        = (const float*)d_in[8];
    const float* w2        = (const float*)d_in[9];
    const float* b2        = (const float*)d_in[10];
    float* out = (float*)d_out;

    const int n_atoms = in_sizes[0] / HID;
    const int n_edges = in_sizes[2];

    // 1) fold edge linear layers
    prep_kernel<<<RBF + 1, HID>>>(w_rbf, b_rbf, w_pair, b_pair);

    // 2) zero accumulators
    {
        int total = n_atoms * RBF;
        int blocks = (total + 255) / 256;
        zero_kernel<<<blocks, 256>>>(n_atoms);
    }

    // 3) scatter pair_feat into S + edge counts
    {
        long long threads = (long long)n_edges * 16;
        int blocks = (int)((threads + 255) / 256);
        scatter_kernel<<<blocks, 256>>>((const float4*)pair_feat, recv_idx, n_edges);
    }

    // 4) fused atom-side chain on tensor cores (pipelined weights)
    {
        const int smem_bytes = 3 * 128 * LDA * sizeof(uint32_t);  // ~198 KB
        static bool attr_set = false;
        if (!attr_set) {
            cudaFuncSetAttribute(atom_kernel,
                                 cudaFuncAttributeMaxDynamicSharedMemorySize,
                                 smem_bytes);
            attr_set = true;
        }
        int blocks = (n_atoms + 127) / 128;
        atom_kernel<<<blocks, 512, smem_bytes>>>(
            atom_feat, w1, b1, w2, b2, out, n_atoms);
    }
}